// round 7
// baseline (speedup 1.0000x reference)
#include <cuda_runtime.h>

// ---------------------------------------------------------------------------
// YOLOv3 loss — 2-launch, flat-parallel sparse version.
// Inputs: 0:p0[B,255,13,13] 1:p1[B,255,26,26] 2:p2[B,255,52,52] (f32)
//         3:targets[B,N,5] f32  4:gt_valid[B,N] (dtype auto)  5:anchors[9,2]
// Output: scalar f32.
//
// Scratch invariants (zero at entry, restored by the LAST block of k_fused):
// g_winner (n+1, 0=none), g_bits dedup bitmask, g_cnt, g_done, g_acc.
// ---------------------------------------------------------------------------

#define NCLS 80
#define MAXB 32
#define MAX_CELLS (MAXB * 3 * (13*13 + 26*26 + 52*52))   // 340,704
#define MAX_TOUCH (3 * 3 * MAXB * 32)                    // 5760 bound

__device__ double       g_acc[2];                      // [loss, num_pos]
__device__ int          g_cnt;
__device__ int          g_done;
__device__ int          g_winner[MAX_CELLS];           // 0=none else n+1
__device__ unsigned int g_bits[(MAX_CELLS + 31) / 32]; // dedup bitmask
__device__ int          g_list[MAX_TOUCH];             // packed (s,b,a,j,i)

__device__ __forceinline__ float sp(float x) {         // fast softplus
    return fmaxf(x, 0.f) + __logf(1.f + __expf(-fabsf(x)));
}
__device__ __forceinline__ float bcef(float x, float t) { return sp(x) - x * t; }

// decode packed cell id -> geometry
struct CellInfo {
    int s, b, a, j, i, H, HW, off;
};
__device__ __forceinline__ CellInfo decode(int pk, int B) {
    CellInfo c;
    c.s = (pk >> 20) & 3;  c.b = (pk >> 14) & 63;
    c.a = (pk >> 12) & 3;  c.j = (pk >> 6) & 63;  c.i = pk & 63;
    c.H   = (c.s == 0) ? 13 : (c.s == 1) ? 26 : 52;
    c.off = (c.s == 0) ? 0 : (c.s == 1) ? B * 3 * 169 : B * 3 * (169 + 676);
    c.HW  = c.H * c.H;
    return c;
}
__device__ __forceinline__ int cell_index(const CellInfo& c) {
    return c.off + (c.b * 3 + c.a) * c.HW + c.j * c.H + c.i;
}

// ===========================================================================
// K1: per-target scatter (winner via atomicMax + dedup touch list).
// ===========================================================================
__global__ void __launch_bounds__(128)
k_targets(const float* __restrict__ targets,
          const unsigned char* __restrict__ gv,
          const float* __restrict__ anchors,
          int B, int N) {
    __shared__ int flags[2];
    if (threadIdx.x < 2) flags[threadIdx.x] = 0;
    __syncthreads();
    for (int p = threadIdx.x; p < B * N; p += blockDim.x) {
        unsigned char v = gv[p];
        if (v == 0x3F) atomicOr(&flags[0], 1);
        if ((p & 3) != 0 && v != 0) atomicOr(&flags[1], 1);
    }
    __syncthreads();
    int mode = flags[0] ? 0 : (flags[1] ? 2 : 1);      // 0=f32 1=i32 2=u8

    int tid = blockIdx.x * blockDim.x + threadIdx.x;
    int total = 3 * B * N;
    if (tid >= total) return;
    int s = tid / (B * N);
    int r = tid % (B * N);
    int b = r / N, n = r % N;

    bool valid;
    if (mode == 0)      valid = ((const float*)gv)[b * N + n] != 0.f;
    else if (mode == 1) valid = ((const int*)gv)[b * N + n]   != 0;
    else                valid = gv[b * N + n] != 0;
    if (!valid) return;

    const float* tg = targets + (size_t)(b * N + n) * 5;
    float gx = tg[0], gy = tg[1], gw = tg[2], gh = tg[3];

    int H   = (s == 0) ? 13 : (s == 1) ? 26 : 52;
    int off = (s == 0) ? 0 : (s == 1) ? B * 3 * 169 : B * 3 * (169 + 676);
    int HW  = H * H;

    float ious[3];
    float best_iou = -1.f; int best = 0;
    #pragma unroll
    for (int j = 0; j < 3; j++) {
        int ai = (2 - s) * 3 + j;                      // ANCHOR_MASKS
        float aw = anchors[ai * 2 + 0] * (1.f / 416.f);
        float ah = anchors[ai * 2 + 1] * (1.f / 416.f);
        float inter = fminf(gw, aw) * fminf(gh, ah);
        float uni   = gw * gh + aw * ah - inter + 1e-16f;
        float iou   = inter / uni;
        ious[j] = iou;
        if (iou > best_iou) { best_iou = iou; best = j; }
    }

    int gi = min((int)(gx * H), H - 1);
    int gj = min((int)(gy * H), H - 1);
    int pbase = (s << 20) | (b << 14) | (gj << 6) | gi; // s:2 b:6 a:2 j:6 i:6

    #pragma unroll
    for (int j = 0; j < 3; j++) {
        bool is_best = (j == best);
        if (is_best || ious[j] > 0.5f) {
            int cell = off + (b * 3 + j) * HW + gj * H + gi;
            if (is_best) atomicMax(&g_winner[cell], n + 1);
            unsigned int m = 1u << (cell & 31);
            if ((atomicOr(&g_bits[cell >> 5], m) & m) == 0) {
                int p = atomicAdd(&g_cnt, 1);
                g_list[p] = pbase | (j << 12);
            }
        }
    }
}

// ===========================================================================
// K2: fused. Segments by blockIdx (class | cell | dense), then the last
// finished block restores scratch invariants and writes the output.
//   class: 1 thread per (cell, 4-class chunk): classes k,k+20,k+40,k+60
//   cell : 1 thread per touched cell: coord/obj losses, noobj correction
//   dense: 0.5*softplus(conf) over all cells (float4 vectorized)
// ===========================================================================
__global__ void __launch_bounds__(256, 8)
k_fused(const float* __restrict__ p0,
        const float* __restrict__ p1,
        const float* __restrict__ p2,
        const float* __restrict__ targets,
        const float* __restrict__ anchors,
        int B, int N, int nCls, int nCell, float* out) {
    int lane = threadIdx.x & 31, w = threadIdx.x >> 5;
    __shared__ double sl[8], sn[8];
    __shared__ int is_last;

    float  fsum = 0.f;     // float partial (class/dense), per-thread
    double dsum = 0.0;     // double partial (cell segment)
    double psum = 0.0;     // num_pos partial
    int    cnt  = g_cnt;
    int    blk  = blockIdx.x;

    if (blk < nCls) {
        // ------------- class segment: (cell, 4-class chunk) per thread ------
        int idx    = blk * 256 + threadIdx.x;            // item id
        int cell_i = idx / 20;                           // list index
        int k      = idx - cell_i * 20;                  // chunk id 0..19
        if (cell_i < cnt) {
            int pk = g_list[cell_i];
            CellInfo c = decode(pk, B);
            int cell = cell_index(c);
            int wn = g_winner[cell];                     // n+1, 0 = none
            if (wn > 0) {
                const float* pred = (c.s == 0) ? p0 : (c.s == 1) ? p1 : p2;
                size_t base = ((size_t)(c.b * 255 + c.a * 85)) * c.HW
                            + (size_t)c.j * c.H + c.i;
                int gcls = (int)targets[(size_t)(c.b * N + (wn - 1)) * 5 + 4];
                // 4 independent scattered loads in flight
                float v0 = pred[base + (size_t)(5 + k)      * c.HW];
                float v1 = pred[base + (size_t)(5 + k + 20) * c.HW];
                float v2 = pred[base + (size_t)(5 + k + 40) * c.HW];
                float v3 = pred[base + (size_t)(5 + k + 60) * c.HW];
                fsum = bcef(v0, (k      == gcls) ? 1.f : 0.f)
                     + bcef(v1, (k + 20 == gcls) ? 1.f : 0.f)
                     + bcef(v2, (k + 40 == gcls) ? 1.f : 0.f)
                     + bcef(v3, (k + 60 == gcls) ? 1.f : 0.f);
            }
        }
    } else if (blk < nCls + nCell) {
        // ------------- cell segment: 1 thread per touched cell --------------
        int cell_i = (blk - nCls) * 256 + threadIdx.x;
        if (cell_i < cnt) {
            int pk = g_list[cell_i];
            CellInfo c = decode(pk, B);
            int cell = cell_index(c);
            const float* pred = (c.s == 0) ? p0 : (c.s == 1) ? p1 : p2;
            size_t base = ((size_t)(c.b * 255 + c.a * 85)) * c.HW
                        + (size_t)c.j * c.H + c.i;
            int wn = g_winner[cell];
            float conf = pred[base + (size_t)4 * c.HW];
            if (wn > 0) {
                float px = pred[base];
                float py = pred[base + (size_t)1 * c.HW];
                float pw = pred[base + (size_t)2 * c.HW];
                float ph = pred[base + (size_t)3 * c.HW];
                const float* tg = targets + (size_t)(c.b * N + (wn - 1)) * 5;
                float gx = tg[0], gy = tg[1], gww = tg[2], ghh = tg[3];
                int ai = (2 - c.s) * 3 + c.a;
                float aw = anchors[ai * 2 + 0] * (1.f / 416.f);
                float ah = anchors[ai * 2 + 1] * (1.f / 416.f);
                float tx = gx * c.H - c.i, ty = gy * c.H - c.j;
                float tw = logf(gww / aw), th = logf(ghh / ah);
                float lcoord = bcef(px, tx) + bcef(py, ty)
                             + (pw - tw) * (pw - tw) + (ph - th) * (ph - th);
                dsum = (double)(5.0f * lcoord + sp(-conf))
                     - 0.5 * (double)sp(conf);           // remove dense noobj
                psum = 1.0;
            } else {
                dsum = -0.5 * (double)sp(conf);          // ignore-only cell
            }
        }
    } else {
        // ------------- dense noobj segment ----------------------------------
        int t  = (blk - nCls - nCell) * 256 + threadIdx.x;
        int q1 = B * 3 * 169;
        int Q  = B * 3 * 845;
        if (t < Q) {
            float sum;
            if (t < q1) {
                int r = t / 169, qi = t - r * 169;
                size_t row = (size_t)((r / 3) * 255 + (r % 3) * 85 + 4);
                float4 v = *(const float4*)(p1 + row * 676 + qi * 4);
                sum = sp(v.x) + sp(v.y) + sp(v.z) + sp(v.w);
                sum += sp(p0[row * 169 + qi]);
            } else {
                int u = t - q1;
                int r = u / 676, qi = u - r * 676;
                size_t row = (size_t)((r / 3) * 255 + (r % 3) * 85 + 4);
                float4 v = *(const float4*)(p2 + row * 2704 + qi * 4);
                sum = sp(v.x) + sp(v.y) + sp(v.z) + sp(v.w);
            }
            fsum = 0.5f * sum;
        }
    }

    // ---------------- single warp butterfly over combined partials ----------
    double dl = dsum + (double)fsum;     // per-thread partial (NO pre-reduction)
    #pragma unroll
    for (int o = 16; o; o >>= 1) {
        dl   += __shfl_xor_sync(0xffffffffu, dl, o);
        psum += __shfl_xor_sync(0xffffffffu, psum, o);
    }
    if (lane == 0) { sl[w] = dl; sn[w] = psum; }
    if (threadIdx.x == 0) is_last = 0;
    __syncthreads();
    if (threadIdx.x == 0) {
        double L = 0.0, P = 0.0;
        #pragma unroll
        for (int k = 0; k < 8; k++) { L += sl[k]; P += sn[k]; }
        if (L != 0.0) atomicAdd(&g_acc[0], L);
        if (P != 0.0) atomicAdd(&g_acc[1], P);
        __threadfence();
        int prev = atomicAdd(&g_done, 1);
        if (prev == (int)gridDim.x - 1) is_last = 1;
    }
    __syncthreads();

    // ---------------- last block: restore invariants + finalize -------------
    if (is_last) {
        for (int k2 = threadIdx.x; k2 < cnt; k2 += blockDim.x) {
            CellInfo c = decode(g_list[k2], B);
            int cell = cell_index(c);
            g_winner[cell] = 0;
            atomicAnd(&g_bits[cell >> 5], ~(1u << (cell & 31)));
        }
        __syncthreads();
        if (threadIdx.x == 0) {
            double l = atomicAdd(&g_acc[0], 0.0);
            double n = atomicAdd(&g_acc[1], 0.0);
            out[0] = (float)((n > 0.0) ? l / n : l / (double)B);
            g_acc[0] = 0.0; g_acc[1] = 0.0;
            g_cnt = 0; g_done = 0;
        }
    }
}

extern "C" void kernel_launch(void* const* d_in, const int* in_sizes, int n_in,
                              void* d_out, int out_size) {
    const float* p0      = (const float*)d_in[0];
    const float* p1      = (const float*)d_in[1];
    const float* p2      = (const float*)d_in[2];
    const float* targets = (const float*)d_in[3];
    const unsigned char* gvalid = (const unsigned char*)d_in[4];
    const float* anchors = (const float*)d_in[5];
    float* out = (float*)d_out;

    int B = in_sizes[0] / (255 * 13 * 13);
    int N = in_sizes[3] / (B * 5);
    if (B > MAXB) B = MAXB;

    int touch_max = 3 * 3 * B * N;                     // runtime list bound
    if (touch_max > MAX_TOUCH) touch_max = MAX_TOUCH;

    int tgt_items = 3 * B * N;
    int nCls  = (touch_max * 20 + 255) / 256;          // 4 classes per thread
    int nCell = (touch_max + 255) / 256;
    int nDense = (B * 3 * 845 + 255) / 256;

    k_targets<<<(tgt_items + 127) / 128, 128>>>(targets, gvalid, anchors, B, N);
    k_fused  <<<nCls + nCell + nDense, 256>>>(p0, p1, p2, targets, anchors,
                                              B, N, nCls, nCell, out);
}

// round 8
// speedup vs baseline: 1.0020x; 1.0020x over previous
#include <cuda_runtime.h>

// ---------------------------------------------------------------------------
// YOLOv3 loss — 3-launch, atomic-free reduction version.
// Inputs: 0:p0[B,255,13,13] 1:p1[B,255,26,26] 2:p2[B,255,52,52] (f32)
//         3:targets[B,N,5] f32  4:gt_valid[B,N] (dtype auto)  5:anchors[9,2]
// Output: scalar f32.
//
// Scratch invariants (zero at entry, restored every call):
//   g_winner (n+1, 0=none) / g_bits — restored inline by sparse warps
//   g_cnt — reset by k_final
// Block results go to g_part via plain stores; k_final (1 block) reduces.
// ---------------------------------------------------------------------------

#define NCLS 80
#define MAXB 32
#define MAX_CELLS (MAXB * 3 * (13*13 + 26*26 + 52*52))   // 340,704
#define MAX_TOUCH (3 * 3 * MAXB * 32)                    // 5760
#define MAX_BLKS  4096

__device__ int          g_cnt;
__device__ int          g_winner[MAX_CELLS];           // 0=none else n+1
__device__ unsigned int g_bits[(MAX_CELLS + 31) / 32]; // dedup bitmask
__device__ int          g_list[MAX_TOUCH];             // packed (s,b,a,j,i)
__device__ double       g_part[2 * MAX_BLKS];          // per-block [loss, npos]

__device__ __forceinline__ float sp(float x) {         // fast softplus
    return fmaxf(x, 0.f) + __logf(1.f + __expf(-fabsf(x)));
}
__device__ __forceinline__ float bcef(float x, float t) { return sp(x) - x * t; }
__device__ __forceinline__ float warp_sum(float v) {
    #pragma unroll
    for (int o = 16; o; o >>= 1) v += __shfl_xor_sync(0xffffffffu, v, o);
    return v;
}

// ===========================================================================
// K1: per-target scatter (winner via atomicMax + dedup touch list).
// (unchanged — proven)
// ===========================================================================
__global__ void __launch_bounds__(128)
k_targets(const float* __restrict__ targets,
          const unsigned char* __restrict__ gv,
          const float* __restrict__ anchors,
          int B, int N) {
    __shared__ int flags[2];
    if (threadIdx.x < 2) flags[threadIdx.x] = 0;
    __syncthreads();
    for (int p = threadIdx.x; p < B * N; p += blockDim.x) {
        unsigned char v = gv[p];
        if (v == 0x3F) atomicOr(&flags[0], 1);
        if ((p & 3) != 0 && v != 0) atomicOr(&flags[1], 1);
    }
    __syncthreads();
    int mode = flags[0] ? 0 : (flags[1] ? 2 : 1);      // 0=f32 1=i32 2=u8

    int tid = blockIdx.x * blockDim.x + threadIdx.x;
    int total = 3 * B * N;
    if (tid >= total) return;
    int s = tid / (B * N);
    int r = tid % (B * N);
    int b = r / N, n = r % N;

    bool valid;
    if (mode == 0)      valid = ((const float*)gv)[b * N + n] != 0.f;
    else if (mode == 1) valid = ((const int*)gv)[b * N + n]   != 0;
    else                valid = gv[b * N + n] != 0;
    if (!valid) return;

    const float* tg = targets + (size_t)(b * N + n) * 5;
    float gx = tg[0], gy = tg[1], gw = tg[2], gh = tg[3];

    int H   = (s == 0) ? 13 : (s == 1) ? 26 : 52;
    int off = (s == 0) ? 0 : (s == 1) ? B * 3 * 169 : B * 3 * (169 + 676);
    int HW  = H * H;

    float ious[3];
    float best_iou = -1.f; int best = 0;
    #pragma unroll
    for (int j = 0; j < 3; j++) {
        int ai = (2 - s) * 3 + j;                      // ANCHOR_MASKS
        float aw = anchors[ai * 2 + 0] * (1.f / 416.f);
        float ah = anchors[ai * 2 + 1] * (1.f / 416.f);
        float inter = fminf(gw, aw) * fminf(gh, ah);
        float uni   = gw * gh + aw * ah - inter + 1e-16f;
        float iou   = inter / uni;
        ious[j] = iou;
        if (iou > best_iou) { best_iou = iou; best = j; }
    }

    int gi = min((int)(gx * H), H - 1);
    int gj = min((int)(gy * H), H - 1);
    int pbase = (s << 20) | (b << 14) | (gj << 6) | gi; // s:2 b:6 a:2 j:6 i:6

    #pragma unroll
    for (int j = 0; j < 3; j++) {
        bool is_best = (j == best);
        if (is_best || ious[j] > 0.5f) {
            int cell = off + (b * 3 + j) * HW + gj * H + gi;
            if (is_best) atomicMax(&g_winner[cell], n + 1);
            unsigned int m = 1u << (cell & 31);
            if ((atomicOr(&g_bits[cell >> 5], m) & m) == 0) {
                int p = atomicAdd(&g_cnt, 1);
                g_list[p] = pbase | (j << 12);
            }
        }
    }
}

// ===========================================================================
// K2: fused dense-noobj + sparse-correction (R5 structure).
// ZERO global atomics to shared addresses: each block stores its partial
// loss/npos pair to g_part[2*blockIdx] with plain STG.
// Sparse warps restore g_winner/g_bits invariants inline (single owner).
// ===========================================================================
__global__ void __launch_bounds__(256, 8)
k_fused(const float* __restrict__ p0,
        const float* __restrict__ p1,
        const float* __restrict__ p2,
        const float* __restrict__ targets,
        const float* __restrict__ anchors,
        int B, int N, int nDense) {
    int lane = threadIdx.x & 31, w = threadIdx.x >> 5;
    __shared__ double sl[8], sn[8];

    if ((int)blockIdx.x < nDense) {
        // ---------------- dense noobj ----------------
        int t  = blockIdx.x * blockDim.x + threadIdx.x;
        int q1 = B * 3 * 169;              // scale-1 quads (== scale-0 elements)
        int Q  = B * 3 * 845;
        float sum = 0.f;
        if (t < Q) {
            if (t < q1) {
                int r = t / 169, qi = t - r * 169;
                size_t row = (size_t)((r / 3) * 255 + (r % 3) * 85 + 4);
                float4 v = *(const float4*)(p1 + row * 676 + qi * 4);
                sum = sp(v.x) + sp(v.y) + sp(v.z) + sp(v.w);
                sum += sp(p0[row * 169 + qi]);
            } else {
                int u = t - q1;
                int r = u / 676, qi = u - r * 676;
                size_t row = (size_t)((r / 3) * 255 + (r % 3) * 85 + 4);
                float4 v = *(const float4*)(p2 + row * 2704 + qi * 4);
                sum = sp(v.x) + sp(v.y) + sp(v.z) + sp(v.w);
            }
        }
        sum = warp_sum(sum);
        if (lane == 0) { sl[w] = 0.5 * (double)sum; sn[w] = 0.0; }
    } else {
        // ---------------- sparse correction: one warp per touched cell ------
        int gw_id = (blockIdx.x - nDense) * 8 + w;
        int cnt = g_cnt;
        double contrib = 0.0, np = 0.0;
        if (gw_id < cnt) {
            int pk = g_list[gw_id];
            int s = (pk >> 20) & 3, b = (pk >> 14) & 63;
            int a = (pk >> 12) & 3, j = (pk >> 6) & 63, i = pk & 63;
            int H   = (s == 0) ? 13 : (s == 1) ? 26 : 52;
            int off = (s == 0) ? 0 : (s == 1) ? B * 3 * 169 : B * 3 * (169 + 676);
            int HW  = H * H;
            const float* pred = (s == 0) ? p0 : (s == 1) ? p1 : p2;
            int cell = off + (b * 3 + a) * HW + j * H + i;
            size_t base = ((size_t)(b * 255 + a * 85)) * HW + (size_t)j * H + i;

            int wn = g_winner[cell];                    // n+1, 0 = none
            float conf = pred[base + (size_t)4 * HW];

            if (wn > 0) {
                const float* tg = targets + (size_t)(b * N + (wn - 1)) * 5;
                int gcls = (int)tg[4];
                float lcls = 0.f;
                #pragma unroll
                for (int c = lane; c < NCLS; c += 32) {
                    float pc = pred[base + (size_t)(5 + c) * HW];
                    lcls += bcef(pc, (c == gcls) ? 1.f : 0.f);
                }
                lcls = warp_sum(lcls);
                if (lane == 0) {
                    float gx = tg[0], gy = tg[1], gww = tg[2], ghh = tg[3];
                    int ai = (2 - s) * 3 + a;
                    float aw = anchors[ai * 2 + 0] * (1.f / 416.f);
                    float ah = anchors[ai * 2 + 1] * (1.f / 416.f);
                    float tx = gx * H - i, ty = gy * H - j;
                    float tw = logf(gww / aw), th = logf(ghh / ah);
                    float px = pred[base];
                    float py = pred[base + (size_t)1 * HW];
                    float pw = pred[base + (size_t)2 * HW];
                    float ph = pred[base + (size_t)3 * HW];
                    float lcoord = bcef(px, tx) + bcef(py, ty)
                                 + (pw - tw) * (pw - tw) + (ph - th) * (ph - th);
                    contrib = (double)(5.0f * lcoord + sp(-conf) + lcls)
                            - 0.5 * (double)sp(conf);
                    np = 1.0;
                }
            } else if (lane == 0) {
                contrib = -0.5 * (double)sp(conf);      // ignore-only cell
            }
            // restore scratch invariant (this warp is the unique owner)
            if (lane == 0) {
                g_winner[cell] = 0;
                atomicAnd(&g_bits[cell >> 5], ~(1u << (cell & 31)));
            }
        }
        if (lane == 0) { sl[w] = contrib; sn[w] = np; }
    }

    __syncthreads();
    if (threadIdx.x == 0) {
        double L = 0.0, P = 0.0;
        #pragma unroll
        for (int k = 0; k < 8; k++) { L += sl[k]; P += sn[k]; }
        g_part[2 * blockIdx.x]     = L;   // plain stores — no contention
        g_part[2 * blockIdx.x + 1] = P;
    }
}

// ===========================================================================
// K3: single-block reduction of per-block partials + finalize + cnt reset.
// ===========================================================================
__global__ void __launch_bounds__(256)
k_final(float* out, int B, int P) {
    __shared__ double sL[8], sP[8];
    int lane = threadIdx.x & 31, w = threadIdx.x >> 5;

    double L = 0.0, Pp = 0.0;
    for (int i = threadIdx.x; i < P; i += 256) {
        L  += g_part[2 * i];
        Pp += g_part[2 * i + 1];
    }
    #pragma unroll
    for (int o = 16; o; o >>= 1) {
        L  += __shfl_xor_sync(0xffffffffu, L, o);
        Pp += __shfl_xor_sync(0xffffffffu, Pp, o);
    }
    if (lane == 0) { sL[w] = L; sP[w] = Pp; }
    __syncthreads();
    if (threadIdx.x == 0) {
        double l = 0.0, n = 0.0;
        #pragma unroll
        for (int k = 0; k < 8; k++) { l += sL[k]; n += sP[k]; }
        out[0] = (float)((n > 0.0) ? l / n : l / (double)B);
        g_cnt = 0;                                    // restore invariant
    }
}

extern "C" void kernel_launch(void* const* d_in, const int* in_sizes, int n_in,
                              void* d_out, int out_size) {
    const float* p0      = (const float*)d_in[0];
    const float* p1      = (const float*)d_in[1];
    const float* p2      = (const float*)d_in[2];
    const float* targets = (const float*)d_in[3];
    const unsigned char* gvalid = (const unsigned char*)d_in[4];
    const float* anchors = (const float*)d_in[5];
    float* out = (float*)d_out;

    int B = in_sizes[0] / (255 * 13 * 13);
    int N = in_sizes[3] / (B * 5);
    if (B > MAXB) B = MAXB;   // scratch bound (shapes fixed at B=32)

    int tgt_items = 3 * B * N;
    int nDense    = (B * 3 * 845 + 255) / 256;          // dense quad blocks
    int touch_max = 3 * 3 * B * N;
    if (touch_max > MAX_TOUCH) touch_max = MAX_TOUCH;
    int nSparse   = (touch_max + 7) / 8;                // 8 warps/block, 1 cell/warp
    int P         = nDense + nSparse;
    if (P > MAX_BLKS) P = MAX_BLKS;                     // (never hit at B=32)

    k_targets<<<(tgt_items + 127) / 128, 128>>>(targets, gvalid, anchors, B, N);
    k_fused  <<<P, 256>>>(p0, p1, p2, targets, anchors, B, N, nDense);
    k_final  <<<1, 256>>>(out, B, P);
}